// round 13
// baseline (speedup 1.0000x reference)
#include <cuda_runtime.h>
#include <cuda_fp16.h>
#include <cstdint>

#define DD   512
#define NB   4
#define LQ   128
#define LM   256
#define NDP  256   // d-pairs

#define N_TICKETS 1920

// Scratch (allocation-free rule: __device__ globals)
__device__ float    g_q[NB * LQ * DD];          // q = input_emb @ Wq^T + b0 (fp32)
__device__ uint32_t g_mp4[NB * 64 * LM * 4];    // mp half2, [n][dp4][m][slot0..3]
__device__ float    g_sc[NB * LQ * LM];         // raw scores (pre-mask/softmax)

// Pipeline state (reset every launch by init_kernel)
__device__ unsigned g_ticket;
__device__ unsigned g_gcnt[NB];    // gemm tiles done per n (target 96 = 32 q + 64 mp)
__device__ unsigned g_sccnt[NB];   // score tasks done per n (target 256)

__device__ __forceinline__ void mma_tf32(
    float& c0, float& c1, float& c2, float& c3,
    uint32_t a0, uint32_t a1, uint32_t a2, uint32_t a3,
    uint32_t b0, uint32_t b1)
{
    asm volatile(
        "mma.sync.aligned.m16n8k8.row.col.f32.tf32.tf32.f32 "
        "{%0,%1,%2,%3}, {%4,%5,%6,%7}, {%8,%9}, {%0,%1,%2,%3};"
        : "+f"(c0), "+f"(c1), "+f"(c2), "+f"(c3)
        : "r"(a0), "r"(a1), "r"(a2), "r"(a3), "r"(b0), "r"(b1));
}

__device__ __forceinline__ void cpa16(uint32_t dst, const void* src)
{
    asm volatile("cp.async.cg.shared.global [%0], [%1], 16;\n"
                 :: "r"(dst), "l"(src));
}

__device__ __forceinline__ __half2 tanh2(__half2 x)
{
    uint32_t xi = *(uint32_t*)&x, ri;
    asm("tanh.approx.f16x2 %0, %1;" : "=r"(ri) : "r"(xi));
    return *(__half2*)&ri;
}

__device__ __forceinline__ __half2 H2(uint32_t u) { return *(__half2*)&u; }

// ---------------------------------------------------------------------------
// init: zero pipeline counters (runs before the persistent kernel each call)
// ---------------------------------------------------------------------------
__global__ void init_kernel()
{
    if (threadIdx.x == 0) g_ticket = 0u;
    if (threadIdx.x < NB) { g_gcnt[threadIdx.x] = 0u; g_sccnt[threadIdx.x] = 0u; }
}

// ---------------------------------------------------------------------------
// GEMM task (tf32 MMA, cp.async double-buffered, XOR-swizzled smem).
// sub < 32: q tile of batch n (rows (n*4+sub/8)*32, cols (sub%8)*64, +bias)
// sub >=32: mp tile (rows (n*8+(sub-32)/8)*32) -> g_mp4 packed half2
// ---------------------------------------------------------------------------
__device__ __forceinline__ void gemm_task(
    char* s_raw, int sub, int n,
    const float* __restrict__ inp, const float* __restrict__ mem,
    const float* __restrict__ W0, const float* __restrict__ b0)
{
    float* As = (float*)s_raw;            // [2][1024]  8KB
    float* Bs = (float*)(s_raw + 8192);   // [2][2048] 16KB

    const float* A;
    int off, r0, e0;
    bool isq;
    if (sub < 32) {
        A = inp; off = 0; isq = true;
        r0 = (n * 4 + (sub >> 3)) * 32; e0 = (sub & 7) * 64;
    } else {
        const int s2 = sub - 32;
        A = mem; off = DD; isq = false;
        r0 = (n * 8 + (s2 >> 3)) * 32; e0 = (s2 & 7) * 64;
    }

    const int t = threadIdx.x;
    const int wid = t >> 5, lane = t & 31;
    const int lx = lane & 3, ly = lane >> 2;
    const int swz = 4 * ly;

    const uint32_t sAs = (uint32_t)__cvta_generic_to_shared(As);
    const uint32_t sBs = (uint32_t)__cvta_generic_to_shared(Bs);

    float c[2][2][4];
#pragma unroll
    for (int mt = 0; mt < 2; mt++)
#pragma unroll
        for (int nt = 0; nt < 2; nt++)
#pragma unroll
            for (int i = 0; i < 4; i++) c[mt][nt][i] = 0.f;

    const float* aptr = A + (size_t)r0 * DD;
    const float* bptr = W0 + (size_t)e0 * (2 * DD) + off;

    auto load_stage = [&](int s, int k0) {
#pragma unroll
        for (int i = 0; i < 2; i++) {
            const int cid = 2 * t + i;
            const int row = cid >> 3, cc = (cid & 7) * 4;
            const int pc = cc ^ ((row & 7) * 4);
            cpa16(sAs + (uint32_t)((s * 1024 + row * 32 + pc) * 4),
                  aptr + (size_t)row * DD + k0 + cc);
        }
#pragma unroll
        for (int i = 0; i < 4; i++) {
            const int cid = t + i * 128;
            const int row = cid >> 3, cc = (cid & 7) * 4;
            const int pc = cc ^ ((row & 7) * 4);
            cpa16(sBs + (uint32_t)((s * 2048 + row * 32 + pc) * 4),
                  bptr + (size_t)row * (2 * DD) + k0 + cc);
        }
        asm volatile("cp.async.commit_group;\n" ::: "memory");
    };

    load_stage(0, 0);

    const uint32_t* AsU = (const uint32_t*)As;
    const uint32_t* BsU = (const uint32_t*)Bs;

    for (int it = 0; it < 16; it++) {
        if (it + 1 < 16) load_stage((it + 1) & 1, (it + 1) * 32);
        else asm volatile("cp.async.commit_group;\n" ::: "memory");
        asm volatile("cp.async.wait_group 1;\n" ::: "memory");
        __syncthreads();

        const int s = it & 1;
        const uint32_t* Ab = AsU + s * 1024;
        const uint32_t* Bb = BsU + s * 2048;
#pragma unroll
        for (int k8 = 0; k8 < 4; k8++) {
            const int c0 = (k8 * 8 + lx) ^ swz;
            const int c1 = c0 ^ 4;
            uint32_t a[2][4], b[2][2];
#pragma unroll
            for (int mt = 0; mt < 2; mt++) {
                const int rA = mt * 16 + ly;
                a[mt][0] = Ab[rA * 32 + c0];
                a[mt][1] = Ab[(rA + 8) * 32 + c0];
                a[mt][2] = Ab[rA * 32 + c1];
                a[mt][3] = Ab[(rA + 8) * 32 + c1];
            }
#pragma unroll
            for (int nt = 0; nt < 2; nt++) {
                const int rB = wid * 16 + nt * 8 + ly;
                b[nt][0] = Bb[rB * 32 + c0];
                b[nt][1] = Bb[rB * 32 + c1];
            }
#pragma unroll
            for (int mt = 0; mt < 2; mt++)
#pragma unroll
                for (int nt = 0; nt < 2; nt++)
                    mma_tf32(c[mt][nt][0], c[mt][nt][1], c[mt][nt][2], c[mt][nt][3],
                             a[mt][0], a[mt][1], a[mt][2], a[mt][3],
                             b[nt][0], b[nt][1]);
        }
        __syncthreads();
    }

    // epilogue
#pragma unroll
    for (int mt = 0; mt < 2; mt++) {
#pragma unroll
        for (int nt = 0; nt < 2; nt++) {
            const int col = e0 + wid * 16 + nt * 8 + 2 * lx;
            const int rA = r0 + mt * 16 + ly;
            if (isq) {
                float bx0 = b0[col], bx1 = b0[col + 1];
                float2 v0 = make_float2(c[mt][nt][0] + bx0, c[mt][nt][1] + bx1);
                float2 v1 = make_float2(c[mt][nt][2] + bx0, c[mt][nt][3] + bx1);
                *(float2*)&g_q[(size_t)rA * DD + col]       = v0;
                *(float2*)&g_q[(size_t)(rA + 8) * DD + col] = v1;
            } else {
                const int n_ = rA >> 8;
                const int m_ = rA & 255;
                const int dp = col >> 1;
                const int dp4 = dp >> 2, slot = dp & 3;
                __half2 u0 = __floats2half2_rn(c[mt][nt][0], c[mt][nt][1]);
                __half2 u1 = __floats2half2_rn(c[mt][nt][2], c[mt][nt][3]);
                uint32_t* base = g_mp4 + (size_t)n_ * (64 * LM * 4) + dp4 * (LM * 4);
                base[m_ * 4 + slot]       = *(uint32_t*)&u0;
                base[(m_ + 8) * 4 + slot] = *(uint32_t*)&u1;
            }
        }
    }
}

// ---------------------------------------------------------------------------
// Score task: 4 warps, warp w -> l = l0+w; thread owns one m = m0+lane.
// sub: l-tile (sub>>3, 4 rows), m-eighth (sub&7, 32 m). Full 512-d sum in
// registers; mp via coalesced uint4 LDG (MLP 4); q/w1 broadcast LDS.128.
// ---------------------------------------------------------------------------
__device__ __forceinline__ void score_task(
    char* s_raw, int sub, int n,
    const float* __restrict__ w1v, const float* __restrict__ b1)
{
    uint4* sq = (uint4*)s_raw;            // [4][64]  4KB
    uint4* sw = (uint4*)(s_raw + 4096);   // [64]     1KB

    const int t = threadIdx.x;
    const int wid = t >> 5, lane = t & 31;
    const int l0 = (sub >> 3) * 4;
    const int m0 = (sub & 7) * 32;

    // fill q table (256 entries, 2 per thread) + w1 table (64)
#pragma unroll
    for (int i = 0; i < 2; i++) {
        const int idx = t + i * 128;
        const int l = idx >> 6, dp4 = idx & 63;
        const float* qp = &g_q[(size_t)(n * LQ + l0 + l) * DD + dp4 * 8];
        float4 v0 = *(const float4*)qp;
        float4 v1 = *(const float4*)(qp + 4);
        __half2 h0 = __floats2half2_rn(v0.x, v0.y);
        __half2 h1 = __floats2half2_rn(v0.z, v0.w);
        __half2 h2 = __floats2half2_rn(v1.x, v1.y);
        __half2 h3 = __floats2half2_rn(v1.z, v1.w);
        sq[l * 64 + dp4] = make_uint4(*(uint32_t*)&h0, *(uint32_t*)&h1,
                                      *(uint32_t*)&h2, *(uint32_t*)&h3);
    }
    if (t < 64) {
        const float* wp = &w1v[t * 8];
        float4 w0 = *(const float4*)wp;
        float4 w1f = *(const float4*)(wp + 4);
        __half2 g0 = __floats2half2_rn(w0.x, w0.y);
        __half2 g1 = __floats2half2_rn(w0.z, w0.w);
        __half2 g2 = __floats2half2_rn(w1f.x, w1f.y);
        __half2 g3 = __floats2half2_rn(w1f.z, w1f.w);
        sw[t] = make_uint4(*(uint32_t*)&g0, *(uint32_t*)&g1,
                           *(uint32_t*)&g2, *(uint32_t*)&g3);
    }
    __syncthreads();

    const int l = wid;
    const int m = m0 + lane;
    const uint4* mp4 = (const uint4*)g_mp4 + (size_t)n * (64 * LM);

    float s = 0.f;
#pragma unroll 4
    for (int g = 0; g < 16; g++) {
        uint4 Av[4];
#pragma unroll
        for (int j = 0; j < 4; j++)
            Av[j] = mp4[(g * 4 + j) * LM + m];
        __half2 a0 = __float2half2_rn(0.f), a1 = __float2half2_rn(0.f);
#pragma unroll
        for (int j = 0; j < 4; j++) {
            const int dp4 = g * 4 + j;
            const uint4 qv = sq[l * 64 + dp4];
            const uint4 wv = sw[dp4];
            a0 = __hfma2(H2(wv.x), tanh2(__hadd2(H2(qv.x), H2(Av[j].x))), a0);
            a1 = __hfma2(H2(wv.y), tanh2(__hadd2(H2(qv.y), H2(Av[j].y))), a1);
            a0 = __hfma2(H2(wv.z), tanh2(__hadd2(H2(qv.z), H2(Av[j].z))), a0);
            a1 = __hfma2(H2(wv.w), tanh2(__hadd2(H2(qv.w), H2(Av[j].w))), a1);
        }
        float2 f = __half22float2(__hadd2(a0, a1));
        s += f.x + f.y;
    }

    g_sc[(size_t)(n * LQ + l0 + l) * LM + m] = s + b1[0];
}

// ---------------------------------------------------------------------------
// Out task: masked softmax of 4 rows + output GEMV for a 128-d slice.
// sub: l-tile (sub>>2, 4 rows), d-split (sub&3, 128 d).
// ---------------------------------------------------------------------------
__device__ __forceinline__ void out_task(
    char* s_raw, int sub, int n,
    const float* __restrict__ mem, const unsigned int* __restrict__ mask,
    float* __restrict__ out)
{
    float* att = (float*)s_raw;   // [4][LM] 4KB

    const int l0 = (sub >> 2) * 4;
    const int d0 = (sub & 3) * 128;
    const int t = threadIdx.x;
    const int w = t >> 5, lane = t & 31;

    {
        const int l = w;
        const float* srow = g_sc + (size_t)(n * LQ + l0 + l) * LM;
        const unsigned int* mrow = mask + (size_t)(n * LQ + l0 + l) * LM;
        const float NEG = -3.402823466e38f;
        float s[8];
        float mx = NEG;
#pragma unroll
        for (int k = 0; k < 8; k++) {
            int m = lane + 32 * k;
            float v = srow[m];
            if (mrow[m] == 0u) v = NEG;   // bool promoted: nonzero bits == true
            s[k] = v;
            mx = fmaxf(mx, v);
        }
#pragma unroll
        for (int o = 16; o > 0; o >>= 1)
            mx = fmaxf(mx, __shfl_xor_sync(0xffffffffu, mx, o));
        float sum = 0.f;
#pragma unroll
        for (int k = 0; k < 8; k++) {
            s[k] = __expf(s[k] - mx);
            sum += s[k];
        }
#pragma unroll
        for (int o = 16; o > 0; o >>= 1)
            sum += __shfl_xor_sync(0xffffffffu, sum, o);
        const float inv = 1.f / sum;
#pragma unroll
        for (int k = 0; k < 8; k++)
            att[l * LM + lane + 32 * k] = s[k] * inv;
    }
    __syncthreads();

    {
        const int l = w;
        const int dbase = d0 + lane * 4;
        const float* memn = mem + (size_t)n * LM * DD + dbase;
        float4 o0 = make_float4(0.f, 0.f, 0.f, 0.f);
#pragma unroll 8
        for (int m = 0; m < LM; m++) {
            const float a = att[l * LM + m];
            const float4 v = *(const float4*)&memn[(size_t)m * DD];
            o0.x = fmaf(a, v.x, o0.x); o0.y = fmaf(a, v.y, o0.y);
            o0.z = fmaf(a, v.z, o0.z); o0.w = fmaf(a, v.w, o0.w);
        }
        *(float4*)&out[(size_t)(n * LQ + l0 + l) * DD + dbase] = o0;
    }
}

// ---------------------------------------------------------------------------
// Persistent scheduler. Tickets (1920 total) interleave batches so score's
// MUFU work overlaps gemm (tensor) and out (L2/FMA) of other batches:
//   g0 g1 s0 g2 s1 o0 g3 s2 o1 s3 o2 o3
// Deps: score(n) waits gcnt[n]==96; out(n) waits sccnt[n]==256.
// Progress-safe: tickets grabbed in order -> minimal unfinished ticket is
// always runnable and held by a resident CTA.
// ---------------------------------------------------------------------------
__global__ __launch_bounds__(128, 4) void persist_kernel(
    const float* __restrict__ inp, const float* __restrict__ mem,
    const unsigned int* __restrict__ mask,
    const float* __restrict__ W0, const float* __restrict__ b0,
    const float* __restrict__ w1v, const float* __restrict__ b1,
    float* __restrict__ out)
{
    __shared__ __align__(16) char s_raw[24576];
    __shared__ unsigned sh_t;
    const int tid = threadIdx.x;

    for (;;) {
        __syncthreads();
        if (tid == 0) sh_t = atomicAdd(&g_ticket, 1u);
        __syncthreads();
        const int t = (int)sh_t;
        if (t >= N_TICKETS) break;

        // decode segment
        const int segs[12]  = {0, 96, 192, 448, 544, 800, 928, 1024, 1280, 1408, 1664, 1792};
        const int types[12] = {0, 0,  1,   0,   1,   2,   0,   1,    2,    1,    2,    2};
        const int nsarr[12] = {0, 1,  0,   2,   1,   0,   3,   2,    1,    3,    2,    3};
        int seg = 11;
#pragma unroll
        for (int i = 11; i >= 1; i--)
            if (t < segs[i]) seg = i - 1;
        const int type = types[seg];
        const int n = nsarr[seg];
        const int sub = t - segs[seg];

        // dependency wait (thread 0 spins, then barrier broadcasts)
        if (tid == 0) {
            if (type == 1) {
                while (*(volatile unsigned*)&g_gcnt[n] < 96u) __nanosleep(128);
            } else if (type == 2) {
                while (*(volatile unsigned*)&g_sccnt[n] < 256u) __nanosleep(128);
            }
        }
        __syncthreads();
        __threadfence();   // acquire: producer data visible to all threads

        if (type == 0)      gemm_task(s_raw, sub, n, inp, mem, W0, b0);
        else if (type == 1) score_task(s_raw, sub, n, w1v, b1);
        else                out_task(s_raw, sub, n, mem, mask, out);

        __threadfence();   // release: publish this task's stores
        __syncthreads();
        if (tid == 0) {
            if (type == 0)      atomicAdd(&g_gcnt[n], 1u);
            else if (type == 1) atomicAdd(&g_sccnt[n], 1u);
        }
    }
}

extern "C" void kernel_launch(void* const* d_in, const int* in_sizes, int n_in,
                              void* d_out, int out_size)
{
    const float*        inp  = (const float*)d_in[0];        // (4,128,512)
    const float*        mem  = (const float*)d_in[1];        // (4,256,512)
    const unsigned int* mask = (const unsigned int*)d_in[2]; // (4,128,256) bool->4B
    const float*        W0   = (const float*)d_in[3];        // (512,1024)
    const float*        b0   = (const float*)d_in[4];        // (512)
    const float*        w1   = (const float*)d_in[5];        // (1,512)
    const float*        b1   = (const float*)d_in[6];        // (1)
    float* out = (float*)d_out;                              // (4,128,512)

    init_kernel<<<1, 32>>>();
    persist_kernel<<<592, 128>>>(inp, mem, mask, W0, b0, w1, b1, out);
}